// round 15
// baseline (speedup 1.0000x reference)
#include <cuda_runtime.h>
#include <cuda.h>
#include <math.h>
#include <stdint.h>

#define TTOK 4096
#define HDIM 2048
#define IDIM 1408
#define NEXP 8
#define FINAL_ELEMS (TTOK*HDIM)
#define MAXROWS (TTOK*2)

#define BMT 256        // TC M tile (both GEMMs)
#define BNT 128        // gate_up N tile
#define BND 256        // down N tile
#define BK 32          // down K tile (SW128)
#define GK 16          // gate_up K tile (SW64)
#define KP 36          // legacy-path smem row stride

// gate_up: 5 stages of (A 16KB + Bg 8KB + Bu 8KB) = 160KB + 4KB ctrl
#define GU_STAGE 32768
#define GU_BASE  4096
#define GU_SMEM  (GU_BASE + 5*GU_STAGE)   // 167936
#define GU_BYTES 32768
// down: 3 stages of (A 32KB + B 32KB)
#define DN_STAGE 65536
#define DN_BASE  4096
#define DN_SMEM  (DN_BASE + 3*DN_STAGE)   // 200704
#define DN_BYTES 65536

// ---------------- scratch ----------------
__device__ int   g_cnt[NEXP];
__device__ int   g_off[NEXP];
__device__ int   g_cur[NEXP];
__device__ int   g_tok[MAXROWS];
__device__ float g_wt [MAXROWS];
__device__ int   g_tidx[TTOK*2];
__device__ float g_tw  [TTOK*2];
__device__ int   g_slot[TTOK*2];
__device__ float g_act[(size_t)MAXROWS*IDIM];
__device__ float g_ys [(size_t)MAXROWS*HDIM];
__device__ float g_xs [(size_t)MAXROWS*HDIM];
__device__ float g_cwg[(size_t)NEXP*IDIM*HDIM];
__device__ float g_cwu[(size_t)NEXP*IDIM*HDIM];
__device__ float g_cwd[(size_t)NEXP*HDIM*IDIM];

// ---------------- common helpers ----------------
__device__ __forceinline__ uint32_t smem_u32(const void* p){
    uint32_t a;
    asm("{ .reg .u64 t; cvta.to.shared.u64 t, %1; cvt.u32.u64 %0, t; }" : "=r"(a) : "l"(p));
    return a;
}
__device__ __forceinline__ float tf32r(float f){
    unsigned u; asm("cvt.rna.tf32.f32 %0, %1;" : "=r"(u) : "f"(f));
    return __uint_as_float(u);
}
__device__ __forceinline__ void mma8(float* c, const uint32_t* a, uint32_t b0, uint32_t b1){
    asm volatile(
      "mma.sync.aligned.m16n8k8.row.col.f32.tf32.tf32.f32 "
      "{%0,%1,%2,%3},{%4,%5,%6,%7},{%8,%9},{%0,%1,%2,%3};\n"
      : "+f"(c[0]),"+f"(c[1]),"+f"(c[2]),"+f"(c[3])
      : "r"(a[0]),"r"(a[1]),"r"(a[2]),"r"(a[3]),"r"(b0),"r"(b1));
}
__device__ __forceinline__ void ldsm4(uint32_t* d, uint32_t addr){
    asm volatile("ldmatrix.sync.aligned.m8n8.x4.shared.b16 {%0,%1,%2,%3}, [%4];"
      : "=r"(d[0]),"=r"(d[1]),"=r"(d[2]),"=r"(d[3]) : "r"(addr));
}

#if defined(__CUDA_ARCH_FEAT_SM103_ALL) || defined(__CUDA_ARCH_FEAT_SM100_ALL)
#define HAS_TC 1
static __device__ __forceinline__ uint64_t make_desc(uint32_t smem_addr){
    const uint64_t base = (uint64_t(2) << 61) | (uint64_t(1) << 46) |
                          (uint64_t(64) << 32) | (uint64_t(1) << 16);
    return base | ((uint64_t)(smem_addr >> 4) & 0x3FFFu);
}
static __device__ __forceinline__ uint64_t make_desc64(uint32_t smem_addr){
    const uint64_t base = (uint64_t(4) << 61) | (uint64_t(1) << 46) |
                          (uint64_t(32) << 32) | (uint64_t(1) << 16);
    return base | ((uint64_t)(smem_addr >> 4) & 0x3FFFu);
}
#define IDESC_N(N) ((1u<<4) | (2u<<7) | (2u<<10) | (((N)/8u)<<17) | (8u<<24))
__device__ __forceinline__ void mma_tf32(uint32_t d, uint64_t ad, uint64_t bd,
                                         uint32_t idesc, uint32_t en){
    asm volatile(
      "{\n\t.reg .pred p;\n\tsetp.ne.u32 p, %4, 0;\n\t"
      "tcgen05.mma.cta_group::1.kind::tf32 [%0], %1, %2, %3, {%5,%5,%5,%5}, p;\n\t}"
      :: "r"(d), "l"(ad), "l"(bd), "r"(idesc), "r"(en), "r"(0u) : "memory");
}
__device__ __forceinline__ void tmem_alloc(uint32_t smem_dst, uint32_t ncols){
    asm volatile("tcgen05.alloc.cta_group::1.sync.aligned.shared::cta.b32 [%0], %1;"
                 :: "r"(smem_dst), "r"(ncols) : "memory");
}
__device__ __forceinline__ void tmem_dealloc(uint32_t tmem, uint32_t ncols){
    asm volatile("tcgen05.dealloc.cta_group::1.sync.aligned.b32 %0, %1;" :: "r"(tmem), "r"(ncols));
}
__device__ __forceinline__ void tmem_relinquish(){
    asm volatile("tcgen05.relinquish_alloc_permit.cta_group::1.sync.aligned;");
}
__device__ __forceinline__ void mma_commit(uint32_t mbar){
    asm volatile("tcgen05.commit.cta_group::1.mbarrier::arrive::one.shared::cluster.b64 [%0];"
                 :: "r"(mbar) : "memory");
}
__device__ __forceinline__ void mbar_init(uint32_t mbar, uint32_t cnt){
    asm volatile("mbarrier.init.shared.b64 [%0], %1;" :: "r"(mbar), "r"(cnt) : "memory");
}
__device__ __forceinline__ void mbar_expect(uint32_t mbar, uint32_t bytes){
    asm volatile("mbarrier.arrive.expect_tx.shared.b64 _, [%0], %1;"
                 :: "r"(mbar), "r"(bytes) : "memory");
}
__device__ __forceinline__ void mbar_wait(uint32_t mbar, uint32_t parity){
    asm volatile(
      "{\n\t.reg .pred P;\n\t"
      "W0_%=:\n\t"
      "mbarrier.try_wait.parity.acquire.cta.shared::cta.b64 P, [%0], %1, 0x989680;\n\t"
      "@P bra W1_%=;\n\t"
      "bra W0_%=;\n\t"
      "W1_%=:\n\t}"
      :: "r"(mbar), "r"(parity) : "memory");
}
__device__ __forceinline__ void tma2d(uint32_t smem, const CUtensorMap* m,
                                      int cx, int cy, uint32_t mbar){
    asm volatile("cp.async.bulk.tensor.2d.shared::cta.global.tile.mbarrier::complete_tx::bytes "
                 "[%0], [%1, {%2, %3}], [%4];"
                 :: "r"(smem), "l"(m), "r"(cx), "r"(cy), "r"(mbar) : "memory");
}
__device__ __forceinline__ void tc_fence_after(){
    asm volatile("tcgen05.fence::after_thread_sync;" ::: "memory");
}
__device__ __forceinline__ void tc_fence_before(){
    asm volatile("tcgen05.fence::before_thread_sync;" ::: "memory");
}
__device__ __forceinline__ void ldtm32(uint32_t* r, uint32_t tmem_addr){
    asm volatile(
        "tcgen05.ld.sync.aligned.32x32b.x32.b32 "
        "{%0, %1, %2, %3, %4, %5, %6, %7, %8, %9, %10, %11, %12, %13, %14, %15, "
        " %16, %17, %18, %19, %20, %21, %22, %23, %24, %25, %26, %27, %28, %29, %30, %31}, [%32];"
        : "=r"(r[0]),"=r"(r[1]),"=r"(r[2]),"=r"(r[3]),"=r"(r[4]),"=r"(r[5]),"=r"(r[6]),"=r"(r[7]),
          "=r"(r[8]),"=r"(r[9]),"=r"(r[10]),"=r"(r[11]),"=r"(r[12]),"=r"(r[13]),"=r"(r[14]),"=r"(r[15]),
          "=r"(r[16]),"=r"(r[17]),"=r"(r[18]),"=r"(r[19]),"=r"(r[20]),"=r"(r[21]),"=r"(r[22]),"=r"(r[23]),
          "=r"(r[24]),"=r"(r[25]),"=r"(r[26]),"=r"(r[27]),"=r"(r[28]),"=r"(r[29]),"=r"(r[30]),"=r"(r[31])
        : "r"(tmem_addr));
}
__device__ __forceinline__ void tmem_wait_ld(){
    asm volatile("tcgen05.wait::ld.sync.aligned;" ::: "memory");
}
#else
#define HAS_TC 0
#endif

// ---------------- kernel 0: weight cvt (+count zero) ----------------
__global__ void k_cvtw(const float4* __restrict__ wg, const float4* __restrict__ wu,
                       const float4* __restrict__ wd, int n4){
    int which = blockIdx.y;
    int i = blockIdx.x*blockDim.x + threadIdx.x;
    if (which == 0 && i < NEXP) g_cnt[i] = 0;
    if (i >= n4) return;
    const float4* src = (which==0) ? wg : (which==1) ? wu : wd;
    float4* dst = (which==0) ? (float4*)g_cwg : (which==1) ? (float4*)g_cwu : (float4*)g_cwd;
    float4 v = src[i];
    v.x=tf32r(v.x); v.y=tf32r(v.y); v.z=tf32r(v.z); v.w=tf32r(v.w);
    dst[i] = v;
}

// ---------------- kernel 1: router ----------------
__global__ void k_router(const float* __restrict__ x, const float* __restrict__ gw,
                         float* __restrict__ logits_out){
    int warp = (blockIdx.x*blockDim.x + threadIdx.x) >> 5;
    int lane = threadIdx.x & 31;
    if (warp >= TTOK) return;
    const float* xr = x + (size_t)warp*HDIM;
    float acc[NEXP];
    #pragma unroll
    for (int e=0;e<NEXP;e++) acc[e]=0.f;
    for (int i=lane;i<HDIM;i+=32){
        float xv = xr[i];
        #pragma unroll
        for (int e=0;e<NEXP;e++) acc[e] += xv * __ldg(&gw[e*HDIM+i]);
    }
    #pragma unroll
    for (int e=0;e<NEXP;e++){
        float v = acc[e];
        #pragma unroll
        for (int o=16;o>0;o>>=1) v += __shfl_xor_sync(0xffffffffu, v, o);
        acc[e]=v;
    }
    if (lane==0){
        float m = acc[0];
        #pragma unroll
        for (int e=1;e<NEXP;e++) m = fmaxf(m, acc[e]);
        float p[NEXP];
        #pragma unroll
        for (int e=0;e<NEXP;e++){ p[e] = expf(acc[e]-m); logits_out[(size_t)warp*NEXP+e] = acc[e]; }
        int i1 = 0;
        #pragma unroll
        for (int e=1;e<NEXP;e++) if (p[e] > p[i1]) i1 = e;
        int i2 = (i1==0)?1:0;
        #pragma unroll
        for (int e=0;e<NEXP;e++) if (e!=i1 && p[e] > p[i2]) i2 = e;
        float w1=p[i1], w2=p[i2], inv = 1.f/(w1+w2);
        g_tidx[warp*2+0]=i1; g_tw[warp*2+0]=w1*inv;
        g_tidx[warp*2+1]=i2; g_tw[warp*2+1]=w2*inv;
        atomicAdd(&g_cnt[i1],1);
        atomicAdd(&g_cnt[i2],1);
    }
}

// ---------------- kernel 2: fused scan + placement (+inverse map) ----------------
__global__ void k_place_scan(){
    int tid = threadIdx.x;
    if (tid == 0){
        int o = 0;
        for (int e=0;e<NEXP;e++){ g_off[e]=o; g_cur[e]=o; o += g_cnt[e]; }
    }
    __syncthreads();
    for (int t = tid; t < TTOK; t += blockDim.x){
        #pragma unroll
        for (int k=0;k<2;k++){
            int e = g_tidx[t*2+k];
            int pos = atomicAdd(&g_cur[e],1);
            g_tok[pos] = t;
            g_wt[pos]  = g_tw[t*2+k];
            g_slot[t*2+k] = pos;
        }
    }
}

// ---------------- kernel 3: gather x into slot order (tf32-rounded) ----------------
__global__ void k_gather(const float* __restrict__ x){
    int slot = blockIdx.x;
    int tok  = g_tok[slot];
    const float4* src = (const float4*)(x + (size_t)tok*HDIM);
    float4* dst = (float4*)(g_xs + (size_t)slot*HDIM);
    for (int i = threadIdx.x; i < HDIM/4; i += blockDim.x){
        float4 v = src[i];
        v.x=tf32r(v.x); v.y=tf32r(v.y); v.z=tf32r(v.z); v.w=tf32r(v.w);
        dst[i] = v;
    }
}

// ---------------- kernel 6: weighted combine ----------------
__global__ void k_combine(float* __restrict__ out){
    int i = blockIdx.x*blockDim.x + threadIdx.x;
    int t = i / (HDIM/4);
    int c = i % (HDIM/4);
    int   s0 = g_slot[t*2+0], s1 = g_slot[t*2+1];
    float w0 = g_tw[t*2+0],   w1 = g_tw[t*2+1];
    float4 y0 = ((const float4*)(g_ys + (size_t)s0*HDIM))[c];
    float4 y1 = ((const float4*)(g_ys + (size_t)s1*HDIM))[c];
    float4 r;
    r.x = __fadd_rn(__fmul_rn(w0,y0.x), __fmul_rn(w1,y1.x));
    r.y = __fadd_rn(__fmul_rn(w0,y0.y), __fmul_rn(w1,y1.y));
    r.z = __fadd_rn(__fmul_rn(w0,y0.z), __fmul_rn(w1,y1.z));
    r.w = __fadd_rn(__fmul_rn(w0,y0.w), __fmul_rn(w1,y1.w));
    ((float4*)out)[i] = r;
}

// ================= GEMM 1: gate+up, fused SiLU (TMA, BM=256) =================
__global__ __launch_bounds__(256,1) __cluster_dims__(1,1,1) void k_gate_up(
        const __grid_constant__ CUtensorMap mxs,
        const __grid_constant__ CUtensorMap mwg,
        const __grid_constant__ CUtensorMap mwu,
        const float* __restrict__ x,
        const float* __restrict__ wg, const float* __restrict__ wu){
    extern __shared__ __align__(1024) char smem[];
    uint32_t sb = smem_u32(smem);

    int e   = blockIdx.z;
    int cnt = g_cnt[e];
    int m0  = blockIdx.x * BMT;
    if (m0 >= cnt) return;
    int base = g_off[e];
    int tid  = threadIdx.x;
    int wid  = tid >> 5, lane = tid & 31;

#if HAS_TC
    const int S = 5, F = 4;
    const int NT = HDIM/GK;   // 128
    int n0 = blockIdx.y * BNT;
    if (wid == 0){
        tmem_alloc(sb + 0, 512);
        tmem_relinquish();
    }
    if (tid == 0){
        #pragma unroll
        for (int s=0;s<S;s++){ mbar_init(sb+16+s*16, 1); mbar_init(sb+24+s*16, 1); }
    }
    __syncthreads();
    uint32_t tmem = *(volatile uint32_t*)(smem + 0);

    int arow = base + m0;
    int brow = e*IDIM + n0;

    if (tid == 0){
        #pragma unroll
        for (int p=0;p<F;p++){
            uint32_t sbase = sb + GU_BASE + p*GU_STAGE;
            uint32_t fb = sb + 16 + p*16;
            mbar_expect(fb, GU_BYTES);
            tma2d(sbase,          &mxs, p*GK, arow, fb);
            tma2d(sbase + 16384,  &mwg, p*GK, brow, fb);
            tma2d(sbase + 24576,  &mwu, p*GK, brow, fb);
        }
        for (int t = 0; t < NT; t++){
            int s = t - (t/S)*S;
            mbar_wait(sb + 16 + s*16, (uint32_t)((t/S)&1));
            uint32_t sbase = sb + GU_BASE + s*GU_STAGE;
            uint64_t bgd = make_desc64(sbase + 16384);
            uint64_t bud = make_desc64(sbase + 24576);
            #pragma unroll
            for (int m=0;m<2;m++){
                uint64_t ad = make_desc64(sbase + m*8192);
                #pragma unroll
                for (int c8=0;c8<2;c8++){
                    mma_tf32(tmem + m*256,       ad + 2*c8, bgd + 2*c8, IDESC_N(BNT), (uint32_t)(t | c8));
                    mma_tf32(tmem + m*256 + 128, ad + 2*c8, bud + 2*c8, IDESC_N(BNT), (uint32_t)(t | c8));
                }
            }
            mma_commit(sb + 24 + s*16);
            int u = t + F;
            if (u < NT){
                int s2 = u - (u/S)*S;
                if (u >= S) mbar_wait(sb + 24 + s2*16, (uint32_t)(((u/S)-1)&1));
                uint32_t s2base = sb + GU_BASE + s2*GU_STAGE;
                uint32_t fb = sb + 16 + s2*16;
                mbar_expect(fb, GU_BYTES);
                tma2d(s2base,         &mxs, u*GK, arow, fb);
                tma2d(s2base + 16384, &mwg, u*GK, brow, fb);
                tma2d(s2base + 24576, &mwu, u*GK, brow, fb);
            }
        }
    }
    __syncthreads();
    #pragma unroll
    for (int s=0;s<S;s++){
        int n_s = (NT - s + S - 1)/S;
        mbar_wait(sb + 24 + s*16, (uint32_t)((n_s-1)&1));
    }
    tc_fence_after();
    {
        int m = wid >> 2;
        int rloc = m*128 + (wid&3)*32 + lane;
        int r    = m0 + rloc;
        #pragma unroll
        for (int it=0; it<4; it++){
            int cb = it*32;
            uint32_t gv[32], uv[32];
            ldtm32(gv, tmem + m*256 + cb);
            ldtm32(uv, tmem + m*256 + 128 + cb);
            tmem_wait_ld();
            if (r < cnt){
                float o[32];
                #pragma unroll
                for (int j=0;j<32;j++){
                    float g = __uint_as_float(gv[j]);
                    float u2 = __uint_as_float(uv[j]);
                    o[j] = tf32r(g/(1.f+expf(-g))*u2);
                }
                float* dst = g_act + (size_t)(base + r)*IDIM + n0 + cb;
                #pragma unroll
                for (int j=0;j<8;j++)
                    *(float4*)(dst + j*4) = make_float4(o[j*4],o[j*4+1],o[j*4+2],o[j*4+3]);
            }
        }
    }
    tc_fence_before();
    __syncthreads();
    if (wid == 0) tmem_dealloc(tmem, 512);
#else
    // ---- legacy fallback (PTX pass only): BM=256 via 2 m-passes of 128 ----
    const uint32_t OFF_A = 0, OFF_BG = 18432, OFF_BU = 27648;
    float (*As)[KP] = (float(*)[KP])(smem + OFF_A);
    float (*Bg)[KP] = (float(*)[KP])(smem + OFF_BG);
    float (*Bu)[KP] = (float(*)[KP])(smem + OFF_BU);
    int* stok = (int*)(smem + 36864);

    const float* wgp = wg + (size_t)e*IDIM*HDIM;
    const float* wup = wu + (size_t)e*IDIM*HDIM;

    int wm = (wid&3)*32, wn = (wid>>2)*32;
    int lr = lane & 7, sel = lane >> 3;
    uint32_t aoff[2], bgoff[2], buoff[2];
    #pragma unroll
    for (int mi=0;mi<2;mi++){
        int row = wm + mi*16 + (sel&1)*8 + lr;
        int c0  = (sel>>1)*4;
        aoff[mi] = sb + OFF_A + (uint32_t)(row*KP + c0)*4u;
    }
    #pragma unroll
    for (int nq=0;nq<2;nq++){
        int row = wn + nq*16 + (sel>>1)*8 + lr;
        int c0  = (sel&1)*4;
        bgoff[nq] = sb + OFF_BG + (uint32_t)(row*KP + c0)*4u;
        buoff[nq] = sb + OFF_BU + (uint32_t)(row*KP + c0)*4u;
    }

    for (int mpass=0; mpass<2; mpass++){
        int m0L = m0 + mpass*128;
        if (m0L >= cnt) break;
        __syncthreads();
        if (tid < 128){
            int r = m0L + tid;
            stok[tid] = (r < cnt) ? g_tok[base + r] : g_tok[base];
        }
        __syncthreads();

        for (int hpass = 0; hpass < 2; hpass++){
            int n0 = blockIdx.y * BNT + hpass*64;
            __syncthreads();

            float cg[2][4][4], cu[2][4][4];
            #pragma unroll
            for (int mi=0;mi<2;mi++)
                #pragma unroll
                for (int ni=0;ni<4;ni++)
                    #pragma unroll
                    for (int q=0;q<4;q++){ cg[mi][ni][q]=0.f; cu[mi][ni][q]=0.f; }

            float4 ra[4], rbg[2], rbu[2];
            #pragma unroll
            for (int j=0;j<4;j++){
                int i = tid + j*256; int row = i>>3, k4 = i&7;
                ra[j] = *(const float4*)(&x[(size_t)stok[row]*HDIM + k4*4]);
            }
            #pragma unroll
            for (int j=0;j<2;j++){
                int i = tid + j*256; int n = i>>3, k4 = i&7;
                rbg[j] = *(const float4*)(&wgp[(size_t)(n0+n)*HDIM + k4*4]);
                rbu[j] = *(const float4*)(&wup[(size_t)(n0+n)*HDIM + k4*4]);
            }
            #pragma unroll
            for (int j=0;j<4;j++){
                int i = tid + j*256; int row = i>>3, k4 = i&7;
                As[row][k4*4+0]=tf32r(ra[j].x); As[row][k4*4+1]=tf32r(ra[j].y);
                As[row][k4*4+2]=tf32r(ra[j].z); As[row][k4*4+3]=tf32r(ra[j].w);
            }
            #pragma unroll
            for (int j=0;j<2;j++){
                int i = tid + j*256; int n = i>>3, k4 = i&7;
                Bg[n][k4*4+0]=tf32r(rbg[j].x); Bg[n][k4*4+1]=tf32r(rbg[j].y);
                Bg[n][k4*4+2]=tf32r(rbg[j].z); Bg[n][k4*4+3]=tf32r(rbg[j].w);
                Bu[n][k4*4+0]=tf32r(rbu[j].x); Bu[n][k4*4+1]=tf32r(rbu[j].y);
                Bu[n][k4*4+2]=tf32r(rbu[j].z); Bu[n][k4*4+3]=tf32r(rbu[j].w);
            }
            __syncthreads();

            for (int kk = BK; kk <= HDIM; kk += BK){
                bool more = (kk < HDIM);
                if (more){
                    #pragma unroll
                    for (int j=0;j<4;j++){
                        int i = tid + j*256; int row = i>>3, k4 = i&7;
                        ra[j] = *(const float4*)(&x[(size_t)stok[row]*HDIM + kk + k4*4]);
                    }
                    #pragma unroll
                    for (int j=0;j<2;j++){
                        int i = tid + j*256; int n = i>>3, k4 = i&7;
                        rbg[j] = *(const float4*)(&wgp[(size_t)(n0+n)*HDIM + kk + k4*4]);
                        rbu[j] = *(const float4*)(&wup[(size_t)(n0+n)*HDIM + kk + k4*4]);
                    }
                }
                #pragma unroll
                for (int k8=0;k8<BK;k8+=8){
                    uint32_t kb = (uint32_t)k8*4u;
                    uint32_t a[2][4], bgf[2][4], buf2[2][4];
                    ldsm4(a[0],  aoff[0]  + kb);
                    ldsm4(a[1],  aoff[1]  + kb);
                    ldsm4(bgf[0], bgoff[0] + kb);
                    ldsm4(bgf[1], bgoff[1] + kb);
                    ldsm4(buf2[0], buoff[0] + kb);
                    ldsm4(buf2[1], buoff[1] + kb);
                    #pragma unroll
                    for (int ni=0;ni<4;ni++){
                        int q = ni>>1, ix = (ni&1)*2;
                        #pragma unroll
                        for (int mi=0;mi<2;mi++){
                            mma8(cg[mi][ni], a[mi], bgf[q][ix], bgf[q][ix+1]);
                            mma8(cu[mi][ni], a[mi], buf2[q][ix], buf2[q][ix+1]);
                        }
                    }
                }
                __syncthreads();
                if (more){
                    #pragma unroll
                    for (int j=0;j<4;j++){
                        int i = tid + j*256; int row = i>>3, k4 = i&7;
                        As[row][k4*4+0]=tf32r(ra[j].x); As[row][k4*4+1]=tf32r(ra[j].y);
                        As[row][k4*4+2]=tf32r(ra[j].z); As[row][k4*4+3]=tf32r(ra[j].w);
                    }
                    #pragma unroll
                    for (int j=0;j<2;j++){
                        int i = tid + j*256; int n = i>>3, k4 = i&7;
                        Bg[n][k4*4+0]=tf32r(rbg[j].x); Bg[n][k4*4+1]=tf32r(rbg[j].y);
                        Bg[n][k4*4+2]=tf32r(rbg[j].z); Bg[n][k4*4+3]=tf32r(rbg[j].w);
                        Bu[n][k4*4+0]=tf32r(rbu[j].x); Bu[n][k4*4+1]=tf32r(rbu[j].y);
                        Bu[n][k4*4+2]=tf32r(rbu[j].z); Bu[n][k4*4+3]=tf32r(rbu[j].w);
                    }
                    __syncthreads();
                }
            }

            int grp = lane>>2, thr = lane&3;
            #pragma unroll
            for (int mi=0;mi<2;mi++){
                #pragma unroll
                for (int ni=0;ni<4;ni++){
                    int ncol = n0 + wn + ni*8 + 2*thr;
                    #pragma unroll
                    for (int h=0;h<2;h++){
                        int r = m0L + wm + mi*16 + grp + h*8;
                        if (r < cnt){
                            size_t ro = (size_t)(base + r)*IDIM;
                            float g0 = cg[mi][ni][h*2+0], g1 = cg[mi][ni][h*2+1];
                            float u0 = cu[mi][ni][h*2+0], u1 = cu[mi][ni][h*2+1];
                            g_act[ro + ncol  ] = g0/(1.f+expf(-g0))*u0;
                            g_act[ro + ncol+1] = g1/(1.f+expf(-g1))*u1;
                        }
                    }
                }
            }
        }
    }
#endif
}

// ================= GEMM 2: down -> per-slot STG (TMA) =================
__global__ __launch_bounds__(256,1) __cluster_dims__(1,1,1) void k_down(
        const __grid_constant__ CUtensorMap mact,
        const __grid_constant__ CUtensorMap mwd,
        const float* __restrict__ wd){
    extern __shared__ __align__(1024) char smem[];
    uint32_t sb = smem_u32(smem);

    int e   = blockIdx.z;
    int cnt = g_cnt[e];
    int m0  = blockIdx.x * BMT;
    if (m0 >= cnt) return;
    int base = g_off[e];
    int tid  = threadIdx.x;
    int wid  = tid >> 5, lane = tid & 31;

#if HAS_TC
    const int S = 3, F = 2;
    const int NT = IDIM/BK;   // 44
    int n0 = blockIdx.y * BND;
    if (wid == 0){
        tmem_alloc(sb + 0, 512);
        tmem_relinquish();
    }
    if (tid == 0){
        #pragma unroll
        for (int s=0;s<S;s++){ mbar_init(sb+16+s*16, 1); mbar_init(sb+24+s*16, 1); }
    }
    __syncthreads();
    uint32_t tmem = *(volatile uint32_t*)(smem + 0);

    int arow = base + m0;
    int brow = e*HDIM + n0;

    if (tid == 0){
        #pragma unroll
        for (int p=0;p<F;p++){
            uint32_t sbase = sb + DN_BASE + p*DN_STAGE;
            uint32_t fb = sb + 16 + p*16;
            mbar_expect(fb, DN_BYTES);
            tma2d(sbase,         &mact, p*BK, arow, fb);
            tma2d(sbase + 32768, &mwd,  p*BK, brow, fb);
        }
        for (int t = 0; t < NT; t++){
            int s = t - (t/S)*S;
            mbar_wait(sb + 16 + s*16, (uint32_t)((t/S)&1));
            uint32_t sbase = sb + DN_BASE + s*DN_STAGE;
            uint64_t bd = make_desc(sbase + 32768);
            #pragma unroll
            for (int m=0;m<2;m++){
                uint64_t ad = make_desc(sbase + m*16384);
                #pragma unroll
                for (int c8=0;c8<4;c8++)
                    mma_tf32(tmem + m*256, ad + 2*c8, bd + 2*c8, IDESC_N(BND), (uint32_t)(t | c8));
            }
            mma_commit(sb + 24 + s*16);
            int u = t + F;
            if (u < NT){
                int s2 = u - (u/S)*S;
                if (u >= S) mbar_wait(sb + 24 + s2*16, (uint32_t)(((u/S)-1)&1));
                uint32_t s2base = sb + DN_BASE + s2*DN_STAGE;
                uint32_t fb = sb + 16 + s2*16;
                mbar_expect(fb, DN_BYTES);
                tma2d(s2base,         &mact, u*BK, arow, fb);
                tma2d(s2base + 32768, &mwd,  u*BK, brow, fb);
            }
        }
    }
    __syncthreads();
    #pragma unroll
    for (int s=0;s<S;s++){
        int n_s = (NT - s + S - 1)/S;
        mbar_wait(sb + 24 + s*16, (uint32_t)((n_s-1)&1));
    }
    tc_fence_after();
    {
        int m = wid >> 2;
        int rloc = m*128 + (wid&3)*32 + lane;
        int r    = m0 + rloc;
        float* dstrow = g_ys + (size_t)(base + r)*HDIM + n0;
        #pragma unroll
        for (int it=0; it<8; it++){
            int cb = it*32;
            uint32_t dv[32];
            ldtm32(dv, tmem + m*256 + cb);
            tmem_wait_ld();
            if (r < cnt){
                #pragma unroll
                for (int j=0;j<8;j++)
                    *(float4*)(dstrow + cb + j*4) = make_float4(
                        __uint_as_float(dv[j*4]),   __uint_as_float(dv[j*4+1]),
                        __uint_as_float(dv[j*4+2]), __uint_as_float(dv[j*4+3]));
            }
        }
    }
    tc_fence_before();
    __syncthreads();
    if (wid == 0) tmem_dealloc(tmem, 512);
#else
    const uint32_t OFF_A = 0, OFF_B = 18432;
    float (*As)[KP] = (float(*)[KP])(smem + OFF_A);
    float (*Bs)[KP] = (float(*)[KP])(smem + OFF_B);
    int*   stok = (int*)(smem + 27648);

    const float* wdp = wd + (size_t)e*HDIM*IDIM;

    int wm = (wid&3)*32, wn = (wid>>2)*32;
    int lr = lane & 7, sel = lane >> 3;
    uint32_t aoff[2], boff[2];
    #pragma unroll
    for (int mi=0;mi<2;mi++){
        int row = wm + mi*16 + (sel&1)*8 + lr;
        int c0  = (sel>>1)*4;
        aoff[mi] = sb + OFF_A + (uint32_t)(row*KP + c0)*4u;
    }
    #pragma unroll
    for (int nq=0;nq<2;nq++){
        int row = wn + nq*16 + (sel>>1)*8 + lr;
        int c0  = (sel&1)*4;
        boff[nq] = sb + OFF_B + (uint32_t)(row*KP + c0)*4u;
    }

    for (int mpass=0; mpass<2; mpass++){
        int m0L = m0 + mpass*128;
        if (m0L >= cnt) break;
        __syncthreads();
        if (tid < 128){
            int r = m0L + tid;
            stok[tid] = (r < cnt) ? g_tok[base + r] : g_tok[base];
        }
        __syncthreads();

        for (int hpass = 0; hpass < 4; hpass++){
            int n0 = blockIdx.y * BND + hpass*64;
            __syncthreads();

            float cc[2][4][4];
            #pragma unroll
            for (int mi=0;mi<2;mi++)
                #pragma unroll
                for (int ni=0;ni<4;ni++)
                    #pragma unroll
                    for (int q=0;q<4;q++) cc[mi][ni][q]=0.f;

            float4 ra[4], rb[2];
            #pragma unroll
            for (int j=0;j<4;j++){
                int i = tid + j*256; int row = i>>3, k4 = i&7;
                int rr = m0L + row; if (rr >= cnt) rr = m0L;
                ra[j] = *(const float4*)(&g_act[(size_t)(base+rr)*IDIM + k4*4]);
            }
            #pragma unroll
            for (int j=0;j<2;j++){
                int i = tid + j*256; int n = i>>3, k4 = i&7;
                rb[j] = *(const float4*)(&wdp[(size_t)(n0+n)*IDIM + k4*4]);
            }
            #pragma unroll
            for (int j=0;j<4;j++){
                int i = tid + j*256; int row = i>>3, k4 = i&7;
                As[row][k4*4+0]=tf32r(ra[j].x); As[row][k4*4+1]=tf32r(ra[j].y);
                As[row][k4*4+2]=tf32r(ra[j].z); As[row][k4*4+3]=tf32r(ra[j].w);
            }
            #pragma unroll
            for (int j=0;j<2;j++){
                int i = tid + j*256; int n = i>>3, k4 = i&7;
                Bs[n][k4*4+0]=tf32r(rb[j].x); Bs[n][k4*4+1]=tf32r(rb[j].y);
                Bs[n][k4*4+2]=tf32r(rb[j].z); Bs[n][k4*4+3]=tf32r(rb[j].w);
            }
            __syncthreads();

            for (int kk = BK; kk <= IDIM; kk += BK){
                bool more = (kk < IDIM);
                if (more){
                    #pragma unroll
                    for (int j=0;j<4;j++){
                        int i = tid + j*256; int row = i>>3, k4 = i&7;
                        int rr = m0L + row; if (rr >= cnt) rr = m0L;
                        ra[j] = *(const float4*)(&g_act[(size_t)(base+rr)*IDIM + kk + k4*4]);
                    }
                    #pragma unroll
                    for (int j=0;j<2;j++){
                        int i = tid + j*256; int n = i>>3, k4 = i&7;
                        rb[j] = *(const float4*)(&wdp[(size_t)(n0+n)*IDIM + kk + k4*4]);
                    }
                }
                #pragma unroll
                for (int k8=0;k8<BK;k8+=8){
                    uint32_t kb = (uint32_t)k8*4u;
                    uint32_t a[2][4], bf[2][4];
                    ldsm4(a[0], aoff[0] + kb);
                    ldsm4(a[1], aoff[1] + kb);
                    ldsm4(bf[0], boff[0] + kb);
                    ldsm4(bf[1], boff[1] + kb);
                    #pragma unroll
                    for (int ni=0;ni<4;ni++){
                        int q = ni>>1, ix = (ni&1)*2;
                        #pragma unroll
                        for (int mi=0;mi<2;mi++)
                            mma8(cc[mi][ni], a[mi], bf[q][ix], bf[q][ix+1]);
                    }
                }
                __syncthreads();
                if (more){
                    #pragma unroll
                    for (int j=0;j<4;j++){
                        int i = tid + j*256; int row = i>>3, k4 = i&7;
                        As[row][k4*4+0]=tf32r(ra[j].x); As[row][k4*4+1]=tf32r(ra[j].y);
                        As[row][k4*4+2]=tf32r(ra[j].z); As[row][k4*4+3]=tf32r(ra[j].w);
                    }
                    #pragma unroll
                    for (int j=0;j<2;j++){
                        int i = tid + j*256; int n = i>>3, k4 = i&7;
                        Bs[n][k4*4+0]=tf32r(rb[j].x); Bs[n][k4*4+1]=tf32r(rb[j].y);
                        Bs[n][k4*4+2]=tf32r(rb[j].z); Bs[n][k4*4+3]=tf32r(rb[j].w);
                    }
                    __syncthreads();
                }
            }

            int grp = lane>>2, thr = lane&3;
            #pragma unroll
            for (int mi=0;mi<2;mi++){
                #pragma unroll
                for (int ni=0;ni<4;ni++){
                    int ncol = n0 + wn + ni*8 + 2*thr;
                    #pragma unroll
                    for (int h=0;h<2;h++){
                        int rloc = wm + mi*16 + grp + h*8;
                        int r = m0L + rloc;
                        if (r < cnt){
                            size_t o = (size_t)(base + r)*HDIM + ncol;
                            g_ys[o  ] = cc[mi][ni][h*2+0];
                            g_ys[o+1] = cc[mi][ni][h*2+1];
                        }
                    }
                }
            }
        }
    }
#endif
}

// ---------------- host: tensormap building ----------------
typedef CUresult (*EncodeTiledFn)(
    CUtensorMap*, CUtensorMapDataType, cuuint32_t, void*,
    const cuuint64_t*, const cuuint64_t*, const cuuint32_t*, const cuuint32_t*,
    CUtensorMapInterleave, CUtensorMapSwizzle, CUtensorMapL2promotion, CUtensorMapFloatOOBfill);

static void build_map(EncodeTiledFn enc, CUtensorMap* m, void* ptr,
                      uint64_t d0, uint64_t d1, uint32_t b0, uint32_t b1,
                      CUtensorMapSwizzle sw){
    cuuint64_t dims[2]    = {d0, d1};
    cuuint64_t strides[1] = {d0 * 4};
    cuuint32_t box[2]     = {b0, b1};
    cuuint32_t es[2]      = {1, 1};
    enc(m, CU_TENSOR_MAP_DATA_TYPE_FLOAT32, 2, ptr, dims, strides, box, es,
        CU_TENSOR_MAP_INTERLEAVE_NONE, sw,
        CU_TENSOR_MAP_L2_PROMOTION_L2_128B, CU_TENSOR_MAP_FLOAT_OOB_FILL_NONE);
}

// ---------------- launch ----------------
extern "C" void kernel_launch(void* const* d_in, const int* in_sizes, int n_in,
                              void* d_out, int out_size){
    const float* x  = (const float*)d_in[0];
    const float* gw = (const float*)d_in[1];
    const float* wg = (const float*)d_in[2];
    const float* wu = (const float*)d_in[3];
    const float* wd = (const float*)d_in[4];
    float* out = (float*)d_out;

    cudaFuncSetAttribute(k_gate_up, cudaFuncAttributeMaxDynamicSharedMemorySize, GU_SMEM);
    cudaFuncSetAttribute(k_down,    cudaFuncAttributeMaxDynamicSharedMemorySize, DN_SMEM);

    void* pfn = nullptr;
    cudaDriverEntryPointQueryResult qr;
    cudaGetDriverEntryPoint("cuTensorMapEncodeTiled", &pfn, cudaEnableDefault, &qr);
    EncodeTiledFn enc = (EncodeTiledFn)pfn;

    void *p_xs=nullptr, *p_wg=nullptr, *p_wu=nullptr, *p_wd=nullptr, *p_act=nullptr;
    cudaGetSymbolAddress(&p_xs,  g_xs);
    cudaGetSymbolAddress(&p_wg,  g_cwg);
    cudaGetSymbolAddress(&p_wu,  g_cwu);
    cudaGetSymbolAddress(&p_wd,  g_cwd);
    cudaGetSymbolAddress(&p_act, g_act);

    CUtensorMap mxs, mwg, mwu, mact, mwd;
    build_map(enc, &mxs,  p_xs,  HDIM, MAXROWS,             GK, BMT, CU_TENSOR_MAP_SWIZZLE_64B);
    build_map(enc, &mwg,  p_wg,  HDIM, (uint64_t)NEXP*IDIM, GK, BNT, CU_TENSOR_MAP_SWIZZLE_64B);
    build_map(enc, &mwu,  p_wu,  HDIM, (uint64_t)NEXP*IDIM, GK, BNT, CU_TENSOR_MAP_SWIZZLE_64B);
    build_map(enc, &mact, p_act, IDIM, MAXROWS,             BK, BMT, CU_TENSOR_MAP_SWIZZLE_128B);
    build_map(enc, &mwd,  p_wd,  IDIM, (uint64_t)NEXP*HDIM, BK, BND, CU_TENSOR_MAP_SWIZZLE_128B);

    // second stream + fork/join events (created once; host-side only)
    static cudaStream_t s2 = nullptr;
    static cudaEvent_t  evFork = nullptr, evJoin = nullptr;
    if (!s2){
        cudaStreamCreateWithFlags(&s2, cudaStreamNonBlocking);
        cudaEventCreateWithFlags(&evFork, cudaEventDisableTiming);
        cudaEventCreateWithFlags(&evJoin, cudaEventDisableTiming);
    }

    const int WN4 = (NEXP*IDIM*HDIM)/4;

    // fork: weight cvt on s2, token-side chain on main stream
    cudaEventRecord(evFork, 0);
    cudaStreamWaitEvent(s2, evFork, 0);
    dim3 gcw(WN4/256, 3);
    k_cvtw<<<gcw, 256, 0, s2>>>((const float4*)wg, (const float4*)wu, (const float4*)wd, WN4);
    cudaEventRecord(evJoin, s2);

    k_router<<<TTOK/4, 128>>>(x, gw, out + FINAL_ELEMS);
    k_place_scan<<<1, 1024>>>();
    k_gather<<<MAXROWS, 128>>>(x);

    // join: GEMMs need both branches
    cudaStreamWaitEvent(0, evJoin, 0);
    dim3 g1(TTOK/BMT, IDIM/BNT, NEXP);   // (16, 11, 8)
    k_gate_up<<<g1, 256, GU_SMEM>>>(mxs, mwg, mwu, x, wg, wu);
    dim3 g2(TTOK/BMT, HDIM/BND, NEXP);   // (16, 8, 8)
    k_down<<<g2, 256, DN_SMEM>>>(mact, mwd, wd);
    k_combine<<<FINAL_ELEMS/4/256, 256>>>(out);
}

// round 16
// speedup vs baseline: 1.0087x; 1.0087x over previous
#include <cuda_runtime.h>
#include <cuda.h>
#include <math.h>
#include <stdint.h>

#define TTOK 4096
#define HDIM 2048
#define IDIM 1408
#define NEXP 8
#define FINAL_ELEMS (TTOK*HDIM)
#define MAXROWS (TTOK*2)

#define BMT 256        // TC M tile (both GEMMs)
#define BNT 128        // gate_up N tile
#define BND 256        // down N tile
#define BK 32          // down K tile (SW128)
#define GK 16          // gate_up K tile (SW64)
#define KP 36          // legacy-path smem row stride

// gate_up: 5 stages of (A 16KB + Bg 8KB + Bu 8KB) = 160KB + 4KB ctrl
#define GU_STAGE 32768
#define GU_BASE  4096
#define GU_SMEM  (GU_BASE + 5*GU_STAGE)   // 167936
#define GU_BYTES 32768
// down: 3 stages of (A 32KB + B 32KB)
#define DN_STAGE 65536
#define DN_BASE  4096
#define DN_SMEM  (DN_BASE + 3*DN_STAGE)   // 200704
#define DN_BYTES 65536

// ---------------- scratch ----------------
__device__ int   g_cnt[NEXP];
__device__ int   g_off[NEXP];
__device__ int   g_cur[NEXP];
__device__ int   g_tok[MAXROWS];
__device__ float g_wt [MAXROWS];
__device__ int   g_tidx[TTOK*2];
__device__ float g_tw  [TTOK*2];
__device__ int   g_slot[TTOK*2];
__device__ float g_act[(size_t)MAXROWS*IDIM];
__device__ float g_ys [(size_t)MAXROWS*HDIM];
__device__ float g_xs [(size_t)MAXROWS*HDIM];
__device__ float g_cwg[(size_t)NEXP*IDIM*HDIM];
__device__ float g_cwu[(size_t)NEXP*IDIM*HDIM];
__device__ float g_cwd[(size_t)NEXP*HDIM*IDIM];

// ---------------- common helpers ----------------
__device__ __forceinline__ uint32_t smem_u32(const void* p){
    uint32_t a;
    asm("{ .reg .u64 t; cvta.to.shared.u64 t, %1; cvt.u32.u64 %0, t; }" : "=r"(a) : "l"(p));
    return a;
}
__device__ __forceinline__ float tf32r(float f){
    unsigned u; asm("cvt.rna.tf32.f32 %0, %1;" : "=r"(u) : "f"(f));
    return __uint_as_float(u);
}
__device__ __forceinline__ void mma8(float* c, const uint32_t* a, uint32_t b0, uint32_t b1){
    asm volatile(
      "mma.sync.aligned.m16n8k8.row.col.f32.tf32.tf32.f32 "
      "{%0,%1,%2,%3},{%4,%5,%6,%7},{%8,%9},{%0,%1,%2,%3};\n"
      : "+f"(c[0]),"+f"(c[1]),"+f"(c[2]),"+f"(c[3])
      : "r"(a[0]),"r"(a[1]),"r"(a[2]),"r"(a[3]),"r"(b0),"r"(b1));
}
__device__ __forceinline__ void ldsm4(uint32_t* d, uint32_t addr){
    asm volatile("ldmatrix.sync.aligned.m8n8.x4.shared.b16 {%0,%1,%2,%3}, [%4];"
      : "=r"(d[0]),"=r"(d[1]),"=r"(d[2]),"=r"(d[3]) : "r"(addr));
}

#if defined(__CUDA_ARCH_FEAT_SM103_ALL) || defined(__CUDA_ARCH_FEAT_SM100_ALL)
#define HAS_TC 1
static __device__ __forceinline__ uint64_t make_desc(uint32_t smem_addr){
    const uint64_t base = (uint64_t(2) << 61) | (uint64_t(1) << 46) |
                          (uint64_t(64) << 32) | (uint64_t(1) << 16);
    return base | ((uint64_t)(smem_addr >> 4) & 0x3FFFu);
}
static __device__ __forceinline__ uint64_t make_desc64(uint32_t smem_addr){
    const uint64_t base = (uint64_t(4) << 61) | (uint64_t(1) << 46) |
                          (uint64_t(32) << 32) | (uint64_t(1) << 16);
    return base | ((uint64_t)(smem_addr >> 4) & 0x3FFFu);
}
#define IDESC_N(N) ((1u<<4) | (2u<<7) | (2u<<10) | (((N)/8u)<<17) | (8u<<24))
__device__ __forceinline__ void mma_tf32(uint32_t d, uint64_t ad, uint64_t bd,
                                         uint32_t idesc, uint32_t en){
    asm volatile(
      "{\n\t.reg .pred p;\n\tsetp.ne.u32 p, %4, 0;\n\t"
      "tcgen05.mma.cta_group::1.kind::tf32 [%0], %1, %2, %3, {%5,%5,%5,%5}, p;\n\t}"
      :: "r"(d), "l"(ad), "l"(bd), "r"(idesc), "r"(en), "r"(0u) : "memory");
}
__device__ __forceinline__ void tmem_alloc(uint32_t smem_dst, uint32_t ncols){
    asm volatile("tcgen05.alloc.cta_group::1.sync.aligned.shared::cta.b32 [%0], %1;"
                 :: "r"(smem_dst), "r"(ncols) : "memory");
}
__device__ __forceinline__ void tmem_dealloc(uint32_t tmem, uint32_t ncols){
    asm volatile("tcgen05.dealloc.cta_group::1.sync.aligned.b32 %0, %1;" :: "r"(tmem), "r"(ncols));
}
__device__ __forceinline__ void tmem_relinquish(){
    asm volatile("tcgen05.relinquish_alloc_permit.cta_group::1.sync.aligned;");
}
__device__ __forceinline__ void mma_commit(uint32_t mbar){
    asm volatile("tcgen05.commit.cta_group::1.mbarrier::arrive::one.shared::cluster.b64 [%0];"
                 :: "r"(mbar) : "memory");
}
__device__ __forceinline__ void mma_commit_mc(uint32_t mbar, uint16_t mask){
    asm volatile("tcgen05.commit.cta_group::1.mbarrier::arrive::one.shared::cluster.multicast::cluster.b64 [%0], %1;"
                 :: "r"(mbar), "h"(mask) : "memory");
}
__device__ __forceinline__ void mbar_init(uint32_t mbar, uint32_t cnt){
    asm volatile("mbarrier.init.shared.b64 [%0], %1;" :: "r"(mbar), "r"(cnt) : "memory");
}
__device__ __forceinline__ void mbar_expect(uint32_t mbar, uint32_t bytes){
    asm volatile("mbarrier.arrive.expect_tx.shared.b64 _, [%0], %1;"
                 :: "r"(mbar), "r"(bytes) : "memory");
}
__device__ __forceinline__ void mbar_wait(uint32_t mbar, uint32_t parity){
    asm volatile(
      "{\n\t.reg .pred P;\n\t"
      "W0_%=:\n\t"
      "mbarrier.try_wait.parity.acquire.cta.shared::cta.b64 P, [%0], %1, 0x989680;\n\t"
      "@P bra W1_%=;\n\t"
      "bra W0_%=;\n\t"
      "W1_%=:\n\t}"
      :: "r"(mbar), "r"(parity) : "memory");
}
__device__ __forceinline__ void tma2d(uint32_t smem, const CUtensorMap* m,
                                      int cx, int cy, uint32_t mbar){
    asm volatile("cp.async.bulk.tensor.2d.shared::cta.global.tile.mbarrier::complete_tx::bytes "
                 "[%0], [%1, {%2, %3}], [%4];"
                 :: "r"(smem), "l"(m), "r"(cx), "r"(cy), "r"(mbar) : "memory");
}
__device__ __forceinline__ void tma2d_mc(uint32_t smem, const CUtensorMap* m,
                                         int cx, int cy, uint32_t mbar, uint16_t mask){
    asm volatile("cp.async.bulk.tensor.2d.shared::cluster.global.tile.mbarrier::complete_tx::bytes.multicast::cluster "
                 "[%0], [%1, {%2, %3}], [%4], %5;"
                 :: "r"(smem), "l"(m), "r"(cx), "r"(cy), "r"(mbar), "h"(mask) : "memory");
}
#define CLUSTER_SYNC() do { \
    asm volatile("barrier.cluster.arrive.aligned;" ::: "memory"); \
    asm volatile("barrier.cluster.wait.aligned;" ::: "memory"); } while(0)
__device__ __forceinline__ void tc_fence_after(){
    asm volatile("tcgen05.fence::after_thread_sync;" ::: "memory");
}
__device__ __forceinline__ void tc_fence_before(){
    asm volatile("tcgen05.fence::before_thread_sync;" ::: "memory");
}
__device__ __forceinline__ void ldtm32(uint32_t* r, uint32_t tmem_addr){
    asm volatile(
        "tcgen05.ld.sync.aligned.32x32b.x32.b32 "
        "{%0, %1, %2, %3, %4, %5, %6, %7, %8, %9, %10, %11, %12, %13, %14, %15, "
        " %16, %17, %18, %19, %20, %21, %22, %23, %24, %25, %26, %27, %28, %29, %30, %31}, [%32];"
        : "=r"(r[0]),"=r"(r[1]),"=r"(r[2]),"=r"(r[3]),"=r"(r[4]),"=r"(r[5]),"=r"(r[6]),"=r"(r[7]),
          "=r"(r[8]),"=r"(r[9]),"=r"(r[10]),"=r"(r[11]),"=r"(r[12]),"=r"(r[13]),"=r"(r[14]),"=r"(r[15]),
          "=r"(r[16]),"=r"(r[17]),"=r"(r[18]),"=r"(r[19]),"=r"(r[20]),"=r"(r[21]),"=r"(r[22]),"=r"(r[23]),
          "=r"(r[24]),"=r"(r[25]),"=r"(r[26]),"=r"(r[27]),"=r"(r[28]),"=r"(r[29]),"=r"(r[30]),"=r"(r[31])
        : "r"(tmem_addr));
}
__device__ __forceinline__ void tmem_wait_ld(){
    asm volatile("tcgen05.wait::ld.sync.aligned;" ::: "memory");
}
#else
#define HAS_TC 0
#endif

// ---------------- kernel 0: weight cvt (+count zero) ----------------
__global__ void k_cvtw(const float4* __restrict__ wg, const float4* __restrict__ wu,
                       const float4* __restrict__ wd, int n4){
    int which = blockIdx.y;
    int i = blockIdx.x*blockDim.x + threadIdx.x;
    if (which == 0 && i < NEXP) g_cnt[i] = 0;
    if (i >= n4) return;
    const float4* src = (which==0) ? wg : (which==1) ? wu : wd;
    float4* dst = (which==0) ? (float4*)g_cwg : (which==1) ? (float4*)g_cwu : (float4*)g_cwd;
    float4 v = src[i];
    v.x=tf32r(v.x); v.y=tf32r(v.y); v.z=tf32r(v.z); v.w=tf32r(v.w);
    dst[i] = v;
}

// ---------------- kernel 1: router ----------------
__global__ void k_router(const float* __restrict__ x, const float* __restrict__ gw,
                         float* __restrict__ logits_out){
    int warp = (blockIdx.x*blockDim.x + threadIdx.x) >> 5;
    int lane = threadIdx.x & 31;
    if (warp >= TTOK) return;
    const float* xr = x + (size_t)warp*HDIM;
    float acc[NEXP];
    #pragma unroll
    for (int e=0;e<NEXP;e++) acc[e]=0.f;
    for (int i=lane;i<HDIM;i+=32){
        float xv = xr[i];
        #pragma unroll
        for (int e=0;e<NEXP;e++) acc[e] += xv * __ldg(&gw[e*HDIM+i]);
    }
    #pragma unroll
    for (int e=0;e<NEXP;e++){
        float v = acc[e];
        #pragma unroll
        for (int o=16;o>0;o>>=1) v += __shfl_xor_sync(0xffffffffu, v, o);
        acc[e]=v;
    }
    if (lane==0){
        float m = acc[0];
        #pragma unroll
        for (int e=1;e<NEXP;e++) m = fmaxf(m, acc[e]);
        float p[NEXP];
        #pragma unroll
        for (int e=0;e<NEXP;e++){ p[e] = expf(acc[e]-m); logits_out[(size_t)warp*NEXP+e] = acc[e]; }
        int i1 = 0;
        #pragma unroll
        for (int e=1;e<NEXP;e++) if (p[e] > p[i1]) i1 = e;
        int i2 = (i1==0)?1:0;
        #pragma unroll
        for (int e=0;e<NEXP;e++) if (e!=i1 && p[e] > p[i2]) i2 = e;
        float w1=p[i1], w2=p[i2], inv = 1.f/(w1+w2);
        g_tidx[warp*2+0]=i1; g_tw[warp*2+0]=w1*inv;
        g_tidx[warp*2+1]=i2; g_tw[warp*2+1]=w2*inv;
        atomicAdd(&g_cnt[i1],1);
        atomicAdd(&g_cnt[i2],1);
    }
}

// ---------------- kernel 2: fused scan + placement (+inverse map) ----------------
__global__ void k_place_scan(){
    int tid = threadIdx.x;
    if (tid == 0){
        int o = 0;
        for (int e=0;e<NEXP;e++){ g_off[e]=o; g_cur[e]=o; o += g_cnt[e]; }
    }
    __syncthreads();
    for (int t = tid; t < TTOK; t += blockDim.x){
        #pragma unroll
        for (int k=0;k<2;k++){
            int e = g_tidx[t*2+k];
            int pos = atomicAdd(&g_cur[e],1);
            g_tok[pos] = t;
            g_wt[pos]  = g_tw[t*2+k];
            g_slot[t*2+k] = pos;
        }
    }
}

// ---------------- kernel 3: gather x into slot order (tf32-rounded) ----------------
__global__ void k_gather(const float* __restrict__ x){
    int slot = blockIdx.x;
    int tok  = g_tok[slot];
    const float4* src = (const float4*)(x + (size_t)tok*HDIM);
    float4* dst = (float4*)(g_xs + (size_t)slot*HDIM);
    for (int i = threadIdx.x; i < HDIM/4; i += blockDim.x){
        float4 v = src[i];
        v.x=tf32r(v.x); v.y=tf32r(v.y); v.z=tf32r(v.z); v.w=tf32r(v.w);
        dst[i] = v;
    }
}

// ---------------- kernel 6: weighted combine ----------------
__global__ void k_combine(float* __restrict__ out){
    int i = blockIdx.x*blockDim.x + threadIdx.x;
    int t = i / (HDIM/4);
    int c = i % (HDIM/4);
    int   s0 = g_slot[t*2+0], s1 = g_slot[t*2+1];
    float w0 = g_tw[t*2+0],   w1 = g_tw[t*2+1];
    float4 y0 = ((const float4*)(g_ys + (size_t)s0*HDIM))[c];
    float4 y1 = ((const float4*)(g_ys + (size_t)s1*HDIM))[c];
    float4 r;
    r.x = __fadd_rn(__fmul_rn(w0,y0.x), __fmul_rn(w1,y1.x));
    r.y = __fadd_rn(__fmul_rn(w0,y0.y), __fmul_rn(w1,y1.y));
    r.z = __fadd_rn(__fmul_rn(w0,y0.z), __fmul_rn(w1,y1.z));
    r.w = __fadd_rn(__fmul_rn(w0,y0.w), __fmul_rn(w1,y1.w));
    ((float4*)out)[i] = r;
}

// ================= GEMM 1: gate+up, fused SiLU (TMA multicast, cluster=2) =================
__global__ __launch_bounds__(256,1) __cluster_dims__(2,1,1) void k_gate_up(
        const __grid_constant__ CUtensorMap mxs,
        const __grid_constant__ CUtensorMap mwg,
        const __grid_constant__ CUtensorMap mwu,
        const float* __restrict__ x,
        const float* __restrict__ wg, const float* __restrict__ wu){
    extern __shared__ __align__(1024) char smem[];
    uint32_t sb = smem_u32(smem);

    int e   = blockIdx.z;
    int cnt = g_cnt[e];
    int m0  = blockIdx.x * BMT;
    int base = g_off[e];
    int tid  = threadIdx.x;
    int wid  = tid >> 5, lane = tid & 31;

#if HAS_TC
    // whole-pair-dead => both CTAs exit before any cluster interaction
    int pairm0 = (int)(blockIdx.x & ~1u) * BMT;
    if (pairm0 >= cnt) return;

    const int S = 5, F = 4;
    const int NT = HDIM/GK;   // 128
    int n0 = blockIdx.y * BNT;
    uint32_t rank;
    asm("mov.u32 %0, %%cluster_ctarank;" : "=r"(rank));

    if (wid == 0){
        tmem_alloc(sb + 0, 512);
        tmem_relinquish();
    }
    if (tid == 0){
        #pragma unroll
        for (int s=0;s<S;s++){ mbar_init(sb+16+s*16, 1); mbar_init(sb+24+s*16, 2); }
    }
    __syncthreads();
    CLUSTER_SYNC();                      // mbarriers visible before any multicast
    uint32_t tmem = *(volatile uint32_t*)(smem + 0);

    int arow = base + m0;                // TMA zero-fills OOB rows for dead upper CTA
    int brow = e*IDIM + n0;

    if (tid == 0){
        #pragma unroll
        for (int p=0;p<F;p++){
            uint32_t sbase = sb + GU_BASE + p*GU_STAGE;
            uint32_t fb = sb + 16 + p*16;
            mbar_expect(fb, GU_BYTES);
            tma2d(sbase, &mxs, p*GK, arow, fb);
            if (rank == 0) tma2d_mc(sbase + 16384, &mwg, p*GK, brow, fb, 3);
            else           tma2d_mc(sbase + 24576, &mwu, p*GK, brow, fb, 3);
        }
        for (int t = 0; t < NT; t++){
            int s = t - (t/S)*S;
            mbar_wait(sb + 16 + s*16, (uint32_t)((t/S)&1));
            uint32_t sbase = sb + GU_BASE + s*GU_STAGE;
            uint64_t bgd = make_desc64(sbase + 16384);
            uint64_t bud = make_desc64(sbase + 24576);
            #pragma unroll
            for (int m=0;m<2;m++){
                uint64_t ad = make_desc64(sbase + m*8192);
                #pragma unroll
                for (int c8=0;c8<2;c8++){
                    mma_tf32(tmem + m*256,       ad + 2*c8, bgd + 2*c8, IDESC_N(BNT), (uint32_t)(t | c8));
                    mma_tf32(tmem + m*256 + 128, ad + 2*c8, bud + 2*c8, IDESC_N(BNT), (uint32_t)(t | c8));
                }
            }
            mma_commit_mc(sb + 24 + s*16, 3);    // arrive empty[s] in BOTH CTAs
            int u = t + F;
            if (u < NT){
                int s2 = u - (u/S)*S;
                if (u >= S) mbar_wait(sb + 24 + s2*16, (uint32_t)(((u/S)-1)&1));
                uint32_t s2base = sb + GU_BASE + s2*GU_STAGE;
                uint32_t fb = sb + 16 + s2*16;
                mbar_expect(fb, GU_BYTES);
                tma2d(s2base, &mxs, u*GK, arow, fb);
                if (rank == 0) tma2d_mc(s2base + 16384, &mwg, u*GK, brow, fb, 3);
                else           tma2d_mc(s2base + 24576, &mwu, u*GK, brow, fb, 3);
            }
        }
    }
    __syncthreads();
    #pragma unroll
    for (int s=0;s<S;s++){
        int n_s = (NT - s + S - 1)/S;
        mbar_wait(sb + 24 + s*16, (uint32_t)((n_s-1)&1));
    }
    tc_fence_after();
    {
        int m = wid >> 2;
        int rloc = m*128 + (wid&3)*32 + lane;
        int r    = m0 + rloc;
        #pragma unroll
        for (int it=0; it<4; it++){
            int cb = it*32;
            uint32_t gv[32], uv[32];
            ldtm32(gv, tmem + m*256 + cb);
            ldtm32(uv, tmem + m*256 + 128 + cb);
            tmem_wait_ld();
            if (r < cnt){
                float o[32];
                #pragma unroll
                for (int j=0;j<32;j++){
                    float g = __uint_as_float(gv[j]);
                    float u2 = __uint_as_float(uv[j]);
                    o[j] = tf32r(g/(1.f+expf(-g))*u2);
                }
                float* dst = g_act + (size_t)(base + r)*IDIM + n0 + cb;
                #pragma unroll
                for (int j=0;j<8;j++)
                    *(float4*)(dst + j*4) = make_float4(o[j*4],o[j*4+1],o[j*4+2],o[j*4+3]);
            }
        }
    }
    tc_fence_before();
    __syncthreads();
    if (wid == 0) tmem_dealloc(tmem, 512);
    CLUSTER_SYNC();                      // no CTA exits while peer TMA/commits in flight
#else
    // ---- legacy fallback (PTX pass only): BM=256 via 2 m-passes of 128, no cluster ops ----
    if (m0 >= cnt) return;
    const uint32_t OFF_A = 0, OFF_BG = 18432, OFF_BU = 27648;
    float (*As)[KP] = (float(*)[KP])(smem + OFF_A);
    float (*Bg)[KP] = (float(*)[KP])(smem + OFF_BG);
    float (*Bu)[KP] = (float(*)[KP])(smem + OFF_BU);
    int* stok = (int*)(smem + 36864);

    const float* wgp = wg + (size_t)e*IDIM*HDIM;
    const float* wup = wu + (size_t)e*IDIM*HDIM;

    int wm = (wid&3)*32, wn = (wid>>2)*32;
    int lr = lane & 7, sel = lane >> 3;
    uint32_t aoff[2], bgoff[2], buoff[2];
    #pragma unroll
    for (int mi=0;mi<2;mi++){
        int row = wm + mi*16 + (sel&1)*8 + lr;
        int c0  = (sel>>1)*4;
        aoff[mi] = sb + OFF_A + (uint32_t)(row*KP + c0)*4u;
    }
    #pragma unroll
    for (int nq=0;nq<2;nq++){
        int row = wn + nq*16 + (sel>>1)*8 + lr;
        int c0  = (sel&1)*4;
        bgoff[nq] = sb + OFF_BG + (uint32_t)(row*KP + c0)*4u;
        buoff[nq] = sb + OFF_BU + (uint32_t)(row*KP + c0)*4u;
    }

    for (int mpass=0; mpass<2; mpass++){
        int m0L = m0 + mpass*128;
        if (m0L >= cnt) break;
        __syncthreads();
        if (tid < 128){
            int r = m0L + tid;
            stok[tid] = (r < cnt) ? g_tok[base + r] : g_tok[base];
        }
        __syncthreads();

        for (int hpass = 0; hpass < 2; hpass++){
            int n0 = blockIdx.y * BNT + hpass*64;
            __syncthreads();

            float cg[2][4][4], cu[2][4][4];
            #pragma unroll
            for (int mi=0;mi<2;mi++)
                #pragma unroll
                for (int ni=0;ni<4;ni++)
                    #pragma unroll
                    for (int q=0;q<4;q++){ cg[mi][ni][q]=0.f; cu[mi][ni][q]=0.f; }

            float4 ra[4], rbg[2], rbu[2];
            #pragma unroll
            for (int j=0;j<4;j++){
                int i = tid + j*256; int row = i>>3, k4 = i&7;
                ra[j] = *(const float4*)(&x[(size_t)stok[row]*HDIM + k4*4]);
            }
            #pragma unroll
            for (int j=0;j<2;j++){
                int i = tid + j*256; int n = i>>3, k4 = i&7;
                rbg[j] = *(const float4*)(&wgp[(size_t)(n0+n)*HDIM + k4*4]);
                rbu[j] = *(const float4*)(&wup[(size_t)(n0+n)*HDIM + k4*4]);
            }
            #pragma unroll
            for (int j=0;j<4;j++){
                int i = tid + j*256; int row = i>>3, k4 = i&7;
                As[row][k4*4+0]=tf32r(ra[j].x); As[row][k4*4+1]=tf32r(ra[j].y);
                As[row][k4*4+2]=tf32r(ra[j].z); As[row][k4*4+3]=tf32r(ra[j].w);
            }
            #pragma unroll
            for (int j=0;j<2;j++){
                int i = tid + j*256; int n = i>>3, k4 = i&7;
                Bg[n][k4*4+0]=tf32r(rbg[j].x); Bg[n][k4*4+1]=tf32r(rbg[j].y);
                Bg[n][k4*4+2]=tf32r(rbg[j].z); Bg[n][k4*4+3]=tf32r(rbg[j].w);
                Bu[n][k4*4+0]=tf32r(rbu[j].x); Bu[n][k4*4+1]=tf32r(rbu[j].y);
                Bu[n][k4*4+2]=tf32r(rbu[j].z); Bu[n][k4*4+3]=tf32r(rbu[j].w);
            }
            __syncthreads();

            for (int kk = BK; kk <= HDIM; kk += BK){
                bool more = (kk < HDIM);
                if (more){
                    #pragma unroll
                    for (int j=0;j<4;j++){
                        int i = tid + j*256; int row = i>>3, k4 = i&7;
                        ra[j] = *(const float4*)(&x[(size_t)stok[row]*HDIM + kk + k4*4]);
                    }
                    #pragma unroll
                    for (int j=0;j<2;j++){
                        int i = tid + j*256; int n = i>>3, k4 = i&7;
                        rbg[j] = *(const float4*)(&wgp[(size_t)(n0+n)*HDIM + kk + k4*4]);
                        rbu[j] = *(const float4*)(&wup[(size_t)(n0+n)*HDIM + kk + k4*4]);
                    }
                }
                #pragma unroll
                for (int k8=0;k8<BK;k8+=8){
                    uint32_t kb = (uint32_t)k8*4u;
                    uint32_t a[2][4], bgf[2][4], buf2[2][4];
                    ldsm4(a[0],  aoff[0]  + kb);
                    ldsm4(a[1],  aoff[1]  + kb);
                    ldsm4(bgf[0], bgoff[0] + kb);
                    ldsm4(bgf[1], bgoff[1] + kb);
                    ldsm4(buf2[0], buoff[0] + kb);
                    ldsm4(buf2[1], buoff[1] + kb);
                    #pragma unroll
                    for (int ni=0;ni<4;ni++){
                        int q = ni>>1, ix = (ni&1)*2;
                        #pragma unroll
                        for (int mi=0;mi<2;mi++){
                            mma8(cg[mi][ni], a[mi], bgf[q][ix], bgf[q][ix+1]);
                            mma8(cu[mi][ni], a[mi], buf2[q][ix], buf2[q][ix+1]);
                        }
                    }
                }
                __syncthreads();
                if (more){
                    #pragma unroll
                    for (int j=0;j<4;j++){
                        int i = tid + j*256; int row = i>>3, k4 = i&7;
                        As[row][k4*4+0]=tf32r(ra[j].x); As[row][k4*4+1]=tf32r(ra[j].y);
                        As[row][k4*4+2]=tf32r(ra[j].z); As[row][k4*4+3]=tf32r(ra[j].w);
                    }
                    #pragma unroll
                    for (int j=0;j<2;j++){
                        int i = tid + j*256; int n = i>>3, k4 = i&7;
                        Bg[n][k4*4+0]=tf32r(rbg[j].x); Bg[n][k4*4+1]=tf32r(rbg[j].y);
                        Bg[n][k4*4+2]=tf32r(rbg[j].z); Bg[n][k4*4+3]=tf32r(rbg[j].w);
                        Bu[n][k4*4+0]=tf32r(rbu[j].x); Bu[n][k4*4+1]=tf32r(rbu[j].y);
                        Bu[n][k4*4+2]=tf32r(rbu[j].z); Bu[n][k4*4+3]=tf32r(rbu[j].w);
                    }
                    __syncthreads();
                }
            }

            int grp = lane>>2, thr = lane&3;
            #pragma unroll
            for (int mi=0;mi<2;mi++){
                #pragma unroll
                for (int ni=0;ni<4;ni++){
                    int ncol = n0 + wn + ni*8 + 2*thr;
                    #pragma unroll
                    for (int h=0;h<2;h++){
                        int r = m0L + wm + mi*16 + grp + h*8;
                        if (r < cnt){
                            size_t ro = (size_t)(base + r)*IDIM;
                            float g0 = cg[mi][ni][h*2+0], g1 = cg[mi][ni][h*2+1];
                            float u0 = cu[mi][ni][h*2+0], u1 = cu[mi][ni][h*2+1];
                            g_act[ro + ncol  ] = g0/(1.f+expf(-g0))*u0;
                            g_act[ro + ncol+1] = g1/(1.f+expf(-g1))*u1;
                        }
                    }
                }
            }
        }
    }
#endif
}

// ================= GEMM 2: down -> per-slot STG (TMA) =================
__global__ __launch_bounds__(256,1) __cluster_dims__(1,1,1) void k_down(
        const __grid_constant__ CUtensorMap mact,
        const __grid_constant__ CUtensorMap mwd,
        const float* __restrict__ wd){
    extern __shared__ __align__(1024) char smem[];
    uint32_t sb = smem_u32(smem);

    int e   = blockIdx.z;
    int cnt = g_cnt[e];
    int m0  = blockIdx.x * BMT;
    if (m0 >= cnt) return;
    int base = g_off[e];
    int tid  = threadIdx.x;
    int wid  = tid >> 5, lane = tid & 31;

#if HAS_TC
    const int S = 3, F = 2;
    const int NT = IDIM/BK;   // 44
    int n0 = blockIdx.y * BND;
    if (wid == 0){
        tmem_alloc(sb + 0, 512);
        tmem_relinquish();
    }
    if (tid == 0){
        #pragma unroll
        for (int s=0;s<S;s++){ mbar_init(sb+16+s*16, 1); mbar_init(sb+24+s*16, 1); }
    }
    __syncthreads();
    uint32_t tmem = *(volatile uint32_t*)(smem + 0);

    int arow = base + m0;
    int brow = e*HDIM + n0;

    if (tid == 0){
        #pragma unroll
        for (int p=0;p<F;p++){
            uint32_t sbase = sb + DN_BASE + p*DN_STAGE;
            uint32_t fb = sb + 16 + p*16;
            mbar_expect(fb, DN_BYTES);
            tma2d(sbase,         &mact, p*BK, arow, fb);
            tma2d(sbase + 32768, &mwd,  p*BK, brow, fb);
        }
        for (int t = 0; t < NT; t++){
            int s = t - (t/S)*S;
            mbar_wait(sb + 16 + s*16, (uint32_t)((t/S)&1));
            uint32_t sbase = sb + DN_BASE + s*DN_STAGE;
            uint64_t bd = make_desc(sbase + 32768);
            #pragma unroll
            for (int m=0;m<2;m++){
                uint64_t ad = make_desc(sbase + m*16384);
                #pragma unroll
                for (int c8=0;c8<4;c8++)
                    mma_tf32(tmem + m*256, ad + 2*c8, bd + 2*c8, IDESC_N(BND), (uint32_t)(t | c8));
            }
            mma_commit(sb + 24 + s*16);
            int u = t + F;
            if (u < NT){
                int s2 = u - (u/S)*S;
                if (u >= S) mbar_wait(sb + 24 + s2*16, (uint32_t)(((u/S)-1)&1));
                uint32_t s2base = sb + DN_BASE + s2*DN_STAGE;
                uint32_t fb = sb + 16 + s2*16;
                mbar_expect(fb, DN_BYTES);
                tma2d(s2base,         &mact, u*BK, arow, fb);
                tma2d(s2base + 32768, &mwd,  u*BK, brow, fb);
            }
        }
    }
    __syncthreads();
    #pragma unroll
    for (int s=0;s<S;s++){
        int n_s = (NT - s + S - 1)/S;
        mbar_wait(sb + 24 + s*16, (uint32_t)((n_s-1)&1));
    }
    tc_fence_after();
    {
        int m = wid >> 2;
        int rloc = m*128 + (wid&3)*32 + lane;
        int r    = m0 + rloc;
        float* dstrow = g_ys + (size_t)(base + r)*HDIM + n0;
        #pragma unroll
        for (int it=0; it<8; it++){
            int cb = it*32;
            uint32_t dv[32];
            ldtm32(dv, tmem + m*256 + cb);
            tmem_wait_ld();
            if (r < cnt){
                #pragma unroll
                for (int j=0;j<8;j++)
                    *(float4*)(dstrow + cb + j*4) = make_float4(
                        __uint_as_float(dv[j*4]),   __uint_as_float(dv[j*4+1]),
                        __uint_as_float(dv[j*4+2]), __uint_as_float(dv[j*4+3]));
            }
        }
    }
    tc_fence_before();
    __syncthreads();
    if (wid == 0) tmem_dealloc(tmem, 512);
#else
    const uint32_t OFF_A = 0, OFF_B = 18432;
    float (*As)[KP] = (float(*)[KP])(smem + OFF_A);
    float (*Bs)[KP] = (float(*)[KP])(smem + OFF_B);
    int*   stok = (int*)(smem + 27648);

    const float* wdp = wd + (size_t)e*HDIM*IDIM;

    int wm = (wid&3)*32, wn = (wid>>2)*32;
    int lr = lane & 7, sel = lane >> 3;
    uint32_t aoff[2], boff[2];
    #pragma unroll
    for (int mi=0;mi<2;mi++){
        int row = wm + mi*16 + (sel&1)*8 + lr;
        int c0  = (sel>>1)*4;
        aoff[mi] = sb + OFF_A + (uint32_t)(row*KP + c0)*4u;
    }
    #pragma unroll
    for (int nq=0;nq<2;nq++){
        int row = wn + nq*16 + (sel>>1)*8 + lr;
        int c0  = (sel&1)*4;
        boff[nq] = sb + OFF_B + (uint32_t)(row*KP + c0)*4u;
    }

    for (int mpass=0; mpass<2; mpass++){
        int m0L = m0 + mpass*128;
        if (m0L >= cnt) break;
        __syncthreads();
        if (tid < 128){
            int r = m0L + tid;
            stok[tid] = (r < cnt) ? g_tok[base + r] : g_tok[base];
        }
        __syncthreads();

        for (int hpass = 0; hpass < 4; hpass++){
            int n0 = blockIdx.y * BND + hpass*64;
            __syncthreads();

            float cc[2][4][4];
            #pragma unroll
            for (int mi=0;mi<2;mi++)
                #pragma unroll
                for (int ni=0;ni<4;ni++)
                    #pragma unroll
                    for (int q=0;q<4;q++) cc[mi][ni][q]=0.f;

            float4 ra[4], rb[2];
            #pragma unroll
            for (int j=0;j<4;j++){
                int i = tid + j*256; int row = i>>3, k4 = i&7;
                int rr = m0L + row; if (rr >= cnt) rr = m0L;
                ra[j] = *(const float4*)(&g_act[(size_t)(base+rr)*IDIM + k4*4]);
            }
            #pragma unroll
            for (int j=0;j<2;j++){
                int i = tid + j*256; int n = i>>3, k4 = i&7;
                rb[j] = *(const float4*)(&wdp[(size_t)(n0+n)*IDIM + k4*4]);
            }
            #pragma unroll
            for (int j=0;j<4;j++){
                int i = tid + j*256; int row = i>>3, k4 = i&7;
                As[row][k4*4+0]=tf32r(ra[j].x); As[row][k4*4+1]=tf32r(ra[j].y);
                As[row][k4*4+2]=tf32r(ra[j].z); As[row][k4*4+3]=tf32r(ra[j].w);
            }
            #pragma unroll
            for (int j=0;j<2;j++){
                int i = tid + j*256; int n = i>>3, k4 = i&7;
                Bs[n][k4*4+0]=tf32r(rb[j].x); Bs[n][k4*4+1]=tf32r(rb[j].y);
                Bs[n][k4*4+2]=tf32r(rb[j].z); Bs[n][k4*4+3]=tf32r(rb[j].w);
            }
            __syncthreads();

            for (int kk = BK; kk <= IDIM; kk += BK){
                bool more = (kk < IDIM);
                if (more){
                    #pragma unroll
                    for (int j=0;j<4;j++){
                        int i = tid + j*256; int row = i>>3, k4 = i&7;
                        int rr = m0L + row; if (rr >= cnt) rr = m0L;
                        ra[j] = *(const float4*)(&g_act[(size_t)(base+rr)*IDIM + kk + k4*4]);
                    }
                    #pragma unroll
                    for (int j=0;j<2;j++){
                        int i = tid + j*256; int n = i>>3, k4 = i&7;
                        rb[j] = *(const float4*)(&wdp[(size_t)(n0+n)*IDIM + kk + k4*4]);
                    }
                }
                #pragma unroll
                for (int k8=0;k8<BK;k8+=8){
                    uint32_t kb = (uint32_t)k8*4u;
                    uint32_t a[2][4], bf[2][4];
                    ldsm4(a[0], aoff[0] + kb);
                    ldsm4(a[1], aoff[1] + kb);
                    ldsm4(bf[0], boff[0] + kb);
                    ldsm4(bf[1], boff[1] + kb);
                    #pragma unroll
                    for (int ni=0;ni<4;ni++){
                        int q = ni>>1, ix = (ni&1)*2;
                        #pragma unroll
                        for (int mi=0;mi<2;mi++)
                            mma8(cc[mi][ni], a[mi], bf[q][ix], bf[q][ix+1]);
                    }
                }
                __syncthreads();
                if (more){
                    #pragma unroll
                    for (int j=0;j<4;j++){
                        int i = tid + j*256; int row = i>>3, k4 = i&7;
                        As[row][k4*4+0]=tf32r(ra[j].x); As[row][k4*4+1]=tf32r(ra[j].y);
                        As[row][k4*4+2]=tf32r(ra[j].z); As[row][k4*4+3]=tf32r(ra[j].w);
                    }
                    #pragma unroll
                    for (int j=0;j<2;j++){
                        int i = tid + j*256; int n = i>>3, k4 = i&7;
                        Bs[n][k4*4+0]=tf32r(rb[j].x); Bs[n][k4*4+1]=tf32r(rb[j].y);
                        Bs[n][k4*4+2]=tf32r(rb[j].z); Bs[n][k4*4+3]=tf32r(rb[j].w);
                    }
                    __syncthreads();
                }
            }

            int grp = lane>>2, thr = lane&3;
            #pragma unroll
            for (int mi=0;mi<2;mi++){
                #pragma unroll
                for (int ni=0;ni<4;ni++){
                    int ncol = n0 + wn + ni*8 + 2*thr;
                    #pragma unroll
                    for (int h=0;h<2;h++){
                        int rloc = wm + mi*16 + grp + h*8;
                        int r = m0L + rloc;
                        if (r < cnt){
                            size_t o = (size_t)(base + r)*HDIM + ncol;
                            g_ys[o  ] = cc[mi][ni][h*2+0];
                            g_ys[o+1] = cc[mi][ni][h*2+1];
                        }
                    }
                }
            }
        }
    }
#endif
}

// ---------------- host: tensormap building ----------------
typedef CUresult (*EncodeTiledFn)(
    CUtensorMap*, CUtensorMapDataType, cuuint32_t, void*,
    const cuuint64_t*, const cuuint64_t*, const cuuint32_t*, const cuuint32_t*,
    CUtensorMapInterleave, CUtensorMapSwizzle, CUtensorMapL2promotion, CUtensorMapFloatOOBfill);

static void build_map(EncodeTiledFn enc, CUtensorMap* m, void* ptr,
                      uint64_t d0, uint64_t d1, uint32_t b0, uint32_t b1,
                      CUtensorMapSwizzle sw){
    cuuint64_t dims[2]    = {d0, d1};
    cuuint64_t strides[1] = {d0 * 4};
    cuuint32_t box[2]     = {b0, b1};
    cuuint32_t es[2]      = {1, 1};
    enc(m, CU_TENSOR_MAP_DATA_TYPE_FLOAT32, 2, ptr, dims, strides, box, es,
        CU_TENSOR_MAP_INTERLEAVE_NONE, sw,
        CU_TENSOR_MAP_L2_PROMOTION_L2_128B, CU_TENSOR_MAP_FLOAT_OOB_FILL_NONE);
}

// ---------------- launch ----------------
extern "C" void kernel_launch(void* const* d_in, const int* in_sizes, int n_in,
                              void* d_out, int out_size){
    const float* x  = (const float*)d_in[0];
    const float* gw = (const float*)d_in[1];
    const float* wg = (const float*)d_in[2];
    const float* wu = (const float*)d_in[3];
    const float* wd = (const float*)d_in[4];
    float* out = (float*)d_out;

    cudaFuncSetAttribute(k_gate_up, cudaFuncAttributeMaxDynamicSharedMemorySize, GU_SMEM);
    cudaFuncSetAttribute(k_down,    cudaFuncAttributeMaxDynamicSharedMemorySize, DN_SMEM);

    void* pfn = nullptr;
    cudaDriverEntryPointQueryResult qr;
    cudaGetDriverEntryPoint("cuTensorMapEncodeTiled", &pfn, cudaEnableDefault, &qr);
    EncodeTiledFn enc = (EncodeTiledFn)pfn;

    void *p_xs=nullptr, *p_wg=nullptr, *p_wu=nullptr, *p_wd=nullptr, *p_act=nullptr;
    cudaGetSymbolAddress(&p_xs,  g_xs);
    cudaGetSymbolAddress(&p_wg,  g_cwg);
    cudaGetSymbolAddress(&p_wu,  g_cwu);
    cudaGetSymbolAddress(&p_wd,  g_cwd);
    cudaGetSymbolAddress(&p_act, g_act);

    CUtensorMap mxs, mwg, mwu, mact, mwd;
    build_map(enc, &mxs,  p_xs,  HDIM, MAXROWS,             GK, BMT, CU_TENSOR_MAP_SWIZZLE_64B);
    build_map(enc, &mwg,  p_wg,  HDIM, (uint64_t)NEXP*IDIM, GK, BNT, CU_TENSOR_MAP_SWIZZLE_64B);
    build_map(enc, &mwu,  p_wu,  HDIM, (uint64_t)NEXP*IDIM, GK, BNT, CU_TENSOR_MAP_SWIZZLE_64B);
    build_map(enc, &mact, p_act, IDIM, MAXROWS,             BK, BMT, CU_TENSOR_MAP_SWIZZLE_128B);
    build_map(enc, &mwd,  p_wd,  IDIM, (uint64_t)NEXP*HDIM, BK, BND, CU_TENSOR_MAP_SWIZZLE_128B);

    const int WN4 = (NEXP*IDIM*HDIM)/4;

    dim3 gcw(WN4/256, 3);
    k_cvtw<<<gcw, 256>>>((const float4*)wg, (const float4*)wu, (const float4*)wd, WN4);
    k_router<<<TTOK/4, 128>>>(x, gw, out + FINAL_ELEMS);
    k_place_scan<<<1, 1024>>>();
    k_gather<<<MAXROWS, 128>>>(x);
    dim3 g1(TTOK/BMT, IDIM/BNT, NEXP);   // (16, 11, 8)
    k_gate_up<<<g1, 256, GU_SMEM>>>(mxs, mwg, mwu, x, wg, wu);
    dim3 g2(TTOK/BMT, HDIM/BND, NEXP);   // (16, 8, 8)
    k_down<<<g2, 256, DN_SMEM>>>(mact, mwd, wd);
    k_combine<<<FINAL_ELEMS/4/256, 256>>>(out);
}